// round 2
// baseline (speedup 1.0000x reference)
#include <cuda_runtime.h>

#define NN 2048
#define DD 8
#define HH 64
#define I_TILE 16
#define J_TILE 64

// Scratch (allocation-free rule: __device__ globals)
__device__ float g_A[NN * HH];
__device__ float g_C[NN * HH];

// A[i,h] = sum_d msg[i,d] * W1[h,d]
// C[j,h] = sum_d msg[j,d] * W1[h,D+d] + b1[h]
__global__ void gnn_prep_kernel(const float* __restrict__ msg,
                                const float* __restrict__ W1,
                                const float* __restrict__ b1) {
    int t = blockIdx.x * blockDim.x + threadIdx.x;  // 0 .. N*H-1
    int h = t & (HH - 1);
    int i = t >> 6;
    float a = 0.f;
    float c = b1[h];
    #pragma unroll
    for (int d = 0; d < DD; d++) {
        float m = msg[i * DD + d];
        a += m * W1[h * 2 * DD + d];
        c += m * W1[h * 2 * DD + DD + d];
    }
    g_A[t] = a;
    g_C[t] = c;
}

// Per block: I_TILE rows i. S[i,h] = sum_j relu(A[i,h] + C[j,h]);
// subtract diagonal; fused GEMV epilogue with W2, b2.
__global__ __launch_bounds__(256, 1)
void gnn_main_kernel(const float* __restrict__ W2,
                     const float* __restrict__ b2,
                     float* __restrict__ out) {
    __shared__ float sC[J_TILE * HH];    // 16 KB
    __shared__ float sVal[I_TILE * HH];  // 4 KB

    int t  = threadIdx.x;        // 0..255
    int h  = t & (HH - 1);       // 0..63
    int ig = t >> 6;             // 0..3
    int i0 = blockIdx.x * I_TILE;

    float a[4], acc[4];
    #pragma unroll
    for (int r = 0; r < 4; r++) {
        a[r]   = g_A[(i0 + ig * 4 + r) * HH + h];
        acc[r] = 0.f;
    }

    for (int j0 = 0; j0 < NN; j0 += J_TILE) {
        // Cooperative tile load: J_TILE*HH = 4096 floats = 1024 float4, 256 threads
        const float4* src = (const float4*)(g_C + j0 * HH);
        float4* dst = (float4*)sC;
        #pragma unroll
        for (int k = 0; k < 4; k++)
            dst[t + k * 256] = src[t + k * 256];
        __syncthreads();

        #pragma unroll 8
        for (int jj = 0; jj < J_TILE; jj++) {
            float c = sC[jj * HH + h];   // conflict-free: lane -> consecutive h
            #pragma unroll
            for (int r = 0; r < 4; r++)
                acc[r] += fmaxf(a[r] + c, 0.f);
        }
        __syncthreads();
    }

    // Subtract the j==i diagonal term and stage for epilogue
    #pragma unroll
    for (int r = 0; r < 4; r++) {
        int il = ig * 4 + r;
        int i  = i0 + il;
        acc[r] -= fmaxf(a[r] + g_C[i * HH + h], 0.f);
        sVal[il * HH + h] = acc[r];
    }
    __syncthreads();

    // Epilogue: out[i,d] = (S-D)[i,:] . W2[d,:] / (N-1) + b2[d]
    if (t < I_TILE * DD) {
        int il = t / DD;
        int d  = t % DD;
        float s = 0.f;
        #pragma unroll
        for (int hh = 0; hh < HH; hh++)
            s += sVal[il * HH + hh] * W2[d * HH + hh];
        out[(i0 + il) * DD + d] = s * (1.f / (float)(NN - 1)) + b2[d];
    }
}

extern "C" void kernel_launch(void* const* d_in, const int* in_sizes, int n_in,
                              void* d_out, int out_size) {
    const float* msg = (const float*)d_in[0];  // [2048, 8]
    const float* W1  = (const float*)d_in[1];  // [64, 16]
    const float* b1  = (const float*)d_in[2];  // [64]
    const float* W2  = (const float*)d_in[3];  // [8, 64]
    const float* b2  = (const float*)d_in[4];  // [8]
    float* out = (float*)d_out;                // [2048, 8]

    (void)in_sizes; (void)n_in; (void)out_size;

    gnn_prep_kernel<<<(NN * HH) / 256, 256>>>(msg, W1, b1);
    gnn_main_kernel<<<NN / I_TILE, 256>>>(W2, b2, out);
}

// round 6
// speedup vs baseline: 1.7008x; 1.7008x over previous
#include <cuda_runtime.h>

#define NN 2048
#define DD 8
#define HH 64

// Scratch (allocation-free rule: __device__ globals)
__device__ float g_A[NN * HH];    // [i][h]
__device__ float g_C[NN * HH];    // [i][h]
__device__ float g_Cs[HH * NN];   // [h][j] sorted ascending
__device__ float g_Suf[HH * NN];  // [h][j] suffix sums of g_Cs

// A[i,h] = msg[i,:].W1[h,:8];  C[j,h] = msg[j,:].W1[h,8:] + b1[h]
// Also initializes out[i,d] = b2[d] (search kernel atomically accumulates).
__global__ void gnn_prep_kernel(const float* __restrict__ msg,
                                const float* __restrict__ W1,
                                const float* __restrict__ b1,
                                const float* __restrict__ b2,
                                float* __restrict__ out) {
    int t = blockIdx.x * blockDim.x + threadIdx.x;  // 0 .. N*H-1
    int h = t & (HH - 1);
    int i = t >> 6;
    float a = 0.f;
    float c = b1[h];
    #pragma unroll
    for (int d = 0; d < DD; d++) {
        float m = msg[i * DD + d];
        a += m * W1[h * 2 * DD + d];
        c += m * W1[h * 2 * DD + DD + d];
    }
    g_A[t] = a;
    g_C[t] = c;
    if (t < NN * DD)
        out[t] = b2[t & (DD - 1)];
}

// One block per h: bitonic-sort the 2048 C values ascending, then suffix-sum.
__global__ __launch_bounds__(1024, 1)
void gnn_sort_kernel() {
    __shared__ float sc[NN];
    __shared__ float bufA[NN];
    __shared__ float bufB[NN];

    int h = blockIdx.x;
    int t = threadIdx.x;  // 0..1023

    sc[t]        = g_C[t * HH + h];
    sc[t + 1024] = g_C[(t + 1024) * HH + h];
    __syncthreads();

    // Bitonic sort ascending, 2048 elems, 2 per thread
    for (int k = 2; k <= NN; k <<= 1) {
        for (int j = k >> 1; j > 0; j >>= 1) {
            #pragma unroll
            for (int e = 0; e < 2; e++) {
                int idx = t + e * 1024;
                int ixj = idx ^ j;
                if (ixj > idx) {
                    bool up = ((idx & k) == 0);
                    float x = sc[idx], y = sc[ixj];
                    if ((x > y) == up) { sc[idx] = y; sc[ixj] = x; }
                }
            }
            __syncthreads();
        }
    }

    // Suffix sums (Hillis-Steele from the right, double-buffered)
    bufA[t]        = sc[t];
    bufA[t + 1024] = sc[t + 1024];
    __syncthreads();
    float* cur = bufA;
    float* nxt = bufB;
    for (int off = 1; off < NN; off <<= 1) {
        #pragma unroll
        for (int e = 0; e < 2; e++) {
            int idx = t + e * 1024;
            float v = cur[idx];
            if (idx + off < NN) v += cur[idx + off];
            nxt[idx] = v;
        }
        __syncthreads();
        float* tmp = cur; cur = nxt; nxt = tmp;
    }

    g_Cs[h * NN + t]          = sc[t];
    g_Cs[h * NN + t + 1024]   = sc[t + 1024];
    g_Suf[h * NN + t]         = cur[t];
    g_Suf[h * NN + t + 1024]  = cur[t + 1024];
}

// Block = (32 i's) x (16 h's). Warp w handles h = hg*16+w, lane handles i.
// S[i,h] = a*(N-k) + suf[k] via binary search; subtract diagonal; partial
// GEMV with W2 and atomicAdd into out.
__global__ __launch_bounds__(512, 2)
void gnn_search_kernel(const float* __restrict__ W2,
                       float* __restrict__ out) {
    __shared__ float sVal[16 * 32];  // [h_local][i_local]

    int t    = threadIdx.x;
    int w    = t >> 5;           // 0..15
    int lane = t & 31;
    int ib   = blockIdx.x >> 2;  // 0..63
    int hg   = blockIdx.x & 3;   // 0..3
    int h    = hg * 16 + w;
    int i    = ib * 32 + lane;

    float a   = g_A[i * HH + h];
    float key = -a;
    const float* Cs = g_Cs + h * NN;

    // First index k with Cs[k] > key  (Cs ascending)
    int lo = 0, hi = NN;
    while (lo < hi) {
        int mid = (lo + hi) >> 1;
        if (Cs[mid] > key) hi = mid; else lo = mid + 1;
    }
    int k = lo;

    float S = a * (float)(NN - k) + (k < NN ? g_Suf[h * NN + k] : 0.f);
    S -= fmaxf(a + g_C[i * HH + h], 0.f);  // remove j == i term

    sVal[w * 32 + lane] = S;
    __syncthreads();

    if (t < 32 * DD) {
        int il = t >> 3;
        int d  = t & 7;
        float v = 0.f;
        #pragma unroll
        for (int hh = 0; hh < 16; hh++)
            v += sVal[hh * 32 + il] * W2[d * HH + hg * 16 + hh];
        atomicAdd(&out[(ib * 32 + il) * DD + d], v * (1.f / (float)(NN - 1)));
    }
}

extern "C" void kernel_launch(void* const* d_in, const int* in_sizes, int n_in,
                              void* d_out, int out_size) {
    const float* msg = (const float*)d_in[0];  // [2048, 8]
    const float* W1  = (const float*)d_in[1];  // [64, 16]
    const float* b1  = (const float*)d_in[2];  // [64]
    const float* W2  = (const float*)d_in[3];  // [8, 64]
    const float* b2  = (const float*)d_in[4];  // [8]
    float* out = (float*)d_out;                // [2048, 8]

    (void)in_sizes; (void)n_in; (void)out_size;

    gnn_prep_kernel<<<(NN * HH) / 256, 256>>>(msg, W1, b1, b2, out);
    gnn_sort_kernel<<<HH, 1024>>>();
    gnn_search_kernel<<<(NN / 32) * (HH / 16), 512>>>(W2, out);
}

// round 7
// speedup vs baseline: 1.7741x; 1.0431x over previous
#include <cuda_runtime.h>

#define NN  2048
#define DD  8
#define HH  64
#define NB  256          // value bins per h
#define TPB 1024
#define EPT (NN / TPB)   // 2 elements / queries per thread

// One block per h. Phases: compute C[:,h] -> min/max -> histogram ->
// suffix scan -> counting-sort scatter -> per-i threshold query -> epilogue.
__global__ __launch_bounds__(TPB, 1)
void gnn_fused_kernel(const float* __restrict__ msg,
                      const float* __restrict__ W1,
                      const float* __restrict__ b1,
                      const float* __restrict__ W2,
                      const float* __restrict__ b2,
                      float* __restrict__ out) {
    __shared__ float sbin[NN];           // c values grouped by bin
    __shared__ int   sCntA[NB + 1];      // scan ping
    __shared__ int   sCntB[NB + 1];      // scan pong
    __shared__ float sSumA[NB + 1];
    __shared__ float sSumB[NB + 1];
    __shared__ int   sStart[NB];
    __shared__ int   sOffs[NB];
    __shared__ float sRedMin[32];
    __shared__ float sRedMax[32];
    __shared__ float sMinMax[2];

    const int t = threadIdx.x;
    const int h = blockIdx.x;

    // Per-h weights (broadcast loads)
    float w1a[DD], w1b[DD];
    #pragma unroll
    for (int d = 0; d < DD; d++) {
        w1a[d] = W1[h * 2 * DD + d];
        w1b[d] = W1[h * 2 * DD + DD + d];
    }
    const float bb1 = b1[h];
    float w2r[DD];
    #pragma unroll
    for (int d = 0; d < DD; d++) w2r[d] = W2[d * HH + h];

    // Zero bin accumulators
    if (t <= NB) { sCntA[t] = 0; sSumA[t] = 0.f; }
    if (t < NB)  { sOffs[t] = 0; }

    // Phase 1: c_j = msg[j]·w1b + b1[h]; track min/max
    float cv[EPT];
    float mn = 1e30f, mx = -1e30f;
    #pragma unroll
    for (int e = 0; e < EPT; e++) {
        int j = t + e * TPB;
        float c = bb1;
        #pragma unroll
        for (int d = 0; d < DD; d++) c += msg[j * DD + d] * w1b[d];
        cv[e] = c;
        mn = fminf(mn, c); mx = fmaxf(mx, c);
    }
    #pragma unroll
    for (int o = 16; o > 0; o >>= 1) {
        mn = fminf(mn, __shfl_xor_sync(~0u, mn, o));
        mx = fmaxf(mx, __shfl_xor_sync(~0u, mx, o));
    }
    if ((t & 31) == 0) { sRedMin[t >> 5] = mn; sRedMax[t >> 5] = mx; }
    __syncthreads();
    if (t == 0) {
        float m0 = 1e30f, m1 = -1e30f;
        #pragma unroll
        for (int w = 0; w < TPB / 32; w++) {
            m0 = fminf(m0, sRedMin[w]); m1 = fmaxf(m1, sRedMax[w]);
        }
        sMinMax[0] = m0; sMinMax[1] = m1;
    }
    __syncthreads();

    const float minv  = sMinMax[0];
    const float range = fmaxf(sMinMax[1] - minv, 1e-20f);
    const float invw  = (float)NB / range;

    // Phase 2: histogram (count + sum per bin)
    int bv[EPT];
    #pragma unroll
    for (int e = 0; e < EPT; e++) {
        int b = min(NB - 1, (int)((cv[e] - minv) * invw));
        bv[e] = b;
        atomicAdd(&sCntA[b], 1);
        atomicAdd(&sSumA[b], cv[e]);
    }
    __syncthreads();

    // Phase 3: inclusive suffix scan over 256 bins (8 Hillis-Steele steps).
    // Index NB is a zero pad so suf[kb+1] is always readable.
    {
        int*   ci = sCntA; int*   co = sCntB;
        float* si = sSumA; float* so = sSumB;
        #pragma unroll
        for (int off = 1; off < NB; off <<= 1) {
            if (t <= NB) {
                int   c = ci[t];
                float s = si[t];
                if (t + off <= NB) { c += ci[t + off]; s += si[t + off]; }
                co[t] = c; so[t] = s;
            }
            __syncthreads();
            int* tc = ci; ci = co; co = tc;
            float* ts = si; si = so; so = ts;
        }
        // 8 steps (even): result back in sCntA / sSumA
        if (t < NB) sStart[t] = NN - sCntA[t];
    }
    __syncthreads();

    // Phase 4: scatter into bin-grouped order
    #pragma unroll
    for (int e = 0; e < EPT; e++) {
        int pos = sStart[bv[e]] + atomicAdd(&sOffs[bv[e]], 1);
        sbin[pos] = cv[e];
    }
    __syncthreads();

    // Phase 5: queries + epilogue. i == j index of this thread's elements,
    // so cv[e] is exactly C[i,h] for the diagonal.
    const float inv = 1.f / (float)(NN - 1);
    #pragma unroll
    for (int e = 0; e < EPT; e++) {
        int i = t + e * TPB;
        float a = 0.f;
        #pragma unroll
        for (int d = 0; d < DD; d++) a += msg[i * DD + d] * w1a[d];

        float key = -a;
        float kbf = (key - minv) * invw;
        int   kb  = (kbf < 0.f) ? -1 : min(NB - 1, (int)kbf);

        // Bins strictly above kb: fully active (c > key  =>  a + c > 0)
        float S = a * (float)sCntA[kb + 1] + sSumA[kb + 1];
        // Shared bin: explicit relu
        if (kb >= 0) {
            int p0 = sStart[kb];
            int p1 = NN - sCntA[kb + 1];   // start + count of bin kb
            for (int p = p0; p < p1; p++)
                S += fmaxf(a + sbin[p], 0.f);
        }
        // Remove the j == i term
        S -= fmaxf(a + cv[e], 0.f);

        // out[i,d] += S * W2[d,h] / (N-1)   (+ b2[d] once, from block h==0)
        #pragma unroll
        for (int d = 0; d < DD; d++) {
            float v = S * w2r[d] * inv;
            if (h == 0) v += b2[d];
            atomicAdd(&out[i * DD + d], v);
        }
    }
}

extern "C" void kernel_launch(void* const* d_in, const int* in_sizes, int n_in,
                              void* d_out, int out_size) {
    const float* msg = (const float*)d_in[0];  // [2048, 8]
    const float* W1  = (const float*)d_in[1];  // [64, 16]
    const float* b1  = (const float*)d_in[2];  // [64]
    const float* W2  = (const float*)d_in[3];  // [8, 64]
    const float* b2  = (const float*)d_in[4];  // [8]
    float* out = (float*)d_out;                // [2048, 8]

    (void)in_sizes; (void)n_in; (void)out_size;

    cudaMemsetAsync(out, 0, NN * DD * sizeof(float));
    gnn_fused_kernel<<<HH, TPB>>>(msg, W1, b1, W2, b2, out);
}

// round 8
// speedup vs baseline: 2.3769x; 1.3398x over previous
#include <cuda_runtime.h>

#define NN  2048
#define DD  8
#define HH  64
#define NB  256

// Per-h bin structures (allocation-free rule: __device__ globals)
__device__ float g_bins[HH * NN];          // [h][p] c-values grouped by bin
__device__ int   g_sufCnt[HH * (NB + 1)];  // inclusive suffix counts (+0 pad)
__device__ float g_sufSum[HH * (NB + 1)];  // inclusive suffix sums   (+0 pad)
__device__ float g_meta[HH * 2];           // [h]{minv, invw}

// One block per h: C[:,h] -> min/max -> histogram -> suffix scan -> scatter.
__global__ __launch_bounds__(512, 1)
void gnn_build_kernel(const float* __restrict__ msg,
                      const float* __restrict__ W1,
                      const float* __restrict__ b1) {
    __shared__ int   sCntA[NB + 1];
    __shared__ int   sCntB[NB + 1];
    __shared__ float sSumA[NB + 1];
    __shared__ float sSumB[NB + 1];
    __shared__ int   sOffs[NB];
    __shared__ float sRedMin[16];
    __shared__ float sRedMax[16];
    __shared__ float sMinMax[2];

    const int t = threadIdx.x;   // 0..511
    const int h = blockIdx.x;

    float w1b[DD];
    #pragma unroll
    for (int d = 0; d < DD; d++) w1b[d] = W1[h * 2 * DD + DD + d];
    const float bb1 = b1[h];

    if (t <= NB) { sCntA[t] = 0; sSumA[t] = 0.f; }
    if (t < NB)  sOffs[t] = 0;

    // c_j and block min/max
    float cv[4];
    float mn = 1e30f, mx = -1e30f;
    #pragma unroll
    for (int e = 0; e < 4; e++) {
        int j = t + e * 512;
        float c = bb1;
        #pragma unroll
        for (int d = 0; d < DD; d++) c += msg[j * DD + d] * w1b[d];
        cv[e] = c;
        mn = fminf(mn, c); mx = fmaxf(mx, c);
    }
    #pragma unroll
    for (int o = 16; o > 0; o >>= 1) {
        mn = fminf(mn, __shfl_xor_sync(~0u, mn, o));
        mx = fmaxf(mx, __shfl_xor_sync(~0u, mx, o));
    }
    if ((t & 31) == 0) { sRedMin[t >> 5] = mn; sRedMax[t >> 5] = mx; }
    __syncthreads();
    if (t == 0) {
        float m0 = 1e30f, m1 = -1e30f;
        #pragma unroll
        for (int w = 0; w < 16; w++) {
            m0 = fminf(m0, sRedMin[w]); m1 = fmaxf(m1, sRedMax[w]);
        }
        sMinMax[0] = m0; sMinMax[1] = m1;
    }
    __syncthreads();

    const float minv = sMinMax[0];
    const float invw = (float)NB / fmaxf(sMinMax[1] - minv, 1e-20f);

    // Histogram
    int bv[4];
    #pragma unroll
    for (int e = 0; e < 4; e++) {
        int b = min(NB - 1, (int)((cv[e] - minv) * invw));
        bv[e] = b;
        atomicAdd(&sCntA[b], 1);
        atomicAdd(&sSumA[b], cv[e]);
    }
    __syncthreads();

    // Inclusive suffix scan over NB+1 (pad at NB stays 0); 8 steps -> back in A
    {
        int*   ci = sCntA; int*   co = sCntB;
        float* si = sSumA; float* so = sSumB;
        #pragma unroll
        for (int off = 1; off < NB; off <<= 1) {
            if (t <= NB) {
                int   c = ci[t];
                float s = si[t];
                if (t + off <= NB) { c += ci[t + off]; s += si[t + off]; }
                co[t] = c; so[t] = s;
            }
            __syncthreads();
            int* tc = ci; ci = co; co = tc;
            float* ts = si; si = so; so = ts;
        }
    }

    // Scatter grouped values; start[b] = NN - sufCnt[b]
    #pragma unroll
    for (int e = 0; e < 4; e++) {
        int b = bv[e];
        int pos = (NN - sCntA[b]) + atomicAdd(&sOffs[b], 1);
        g_bins[h * NN + pos] = cv[e];
    }

    if (t <= NB) {
        g_sufCnt[h * (NB + 1) + t] = sCntA[t];
        g_sufSum[h * (NB + 1) + t] = sSumA[t];
    }
    if (t == 0) { g_meta[2 * h] = minv; g_meta[2 * h + 1] = invw; }
}

// Block = 4 i's x 64 h's. Thread (il,h): S[i,h] via suffix tables + shared-bin
// relu scan; SMEM reduce over h -> out written once, no atomics.
__global__ __launch_bounds__(256, 6)
void gnn_query_kernel(const float* __restrict__ msg,
                      const float* __restrict__ W1,
                      const float* __restrict__ b1,
                      const float* __restrict__ W2,
                      const float* __restrict__ b2,
                      float* __restrict__ out) {
    __shared__ float sVal[HH * 4];   // [h][il]

    const int t  = threadIdx.x;
    const int h  = t & 63;
    const int il = t >> 6;           // 0..3
    const int i  = blockIdx.x * 4 + il;

    // msg row (broadcast across the 64 lanes sharing il)
    float m[DD];
    {
        const float4* mp = (const float4*)(msg + i * DD);
        float4 v0 = mp[0], v1 = mp[1];
        m[0] = v0.x; m[1] = v0.y; m[2] = v0.z; m[3] = v0.w;
        m[4] = v1.x; m[5] = v1.y; m[6] = v1.z; m[7] = v1.w;
    }

    float a = 0.f, cdi = b1[h];
    #pragma unroll
    for (int d = 0; d < DD; d++) {
        a   += m[d] * W1[h * 2 * DD + d];
        cdi += m[d] * W1[h * 2 * DD + DD + d];
    }

    const float minv = g_meta[2 * h];
    const float invw = g_meta[2 * h + 1];
    const float key  = -a;
    const float kbf  = (key - minv) * invw;
    const int   kb   = (kbf < 0.f) ? -1 : min(NB - 1, (int)kbf);

    const int   base = h * (NB + 1);
    const int   cnt  = g_sufCnt[base + kb + 1];
    float S = a * (float)cnt + g_sufSum[base + kb + 1];

    if (kb >= 0) {
        int p0 = NN - g_sufCnt[base + kb];
        int p1 = NN - cnt;
        const float* B = g_bins + h * NN;
        #pragma unroll 4
        for (int p = p0; p < p1; p++)
            S += fmaxf(a + B[p], 0.f);
    }
    S -= fmaxf(a + cdi, 0.f);   // remove j == i term

    sVal[h * 4 + il] = S;
    __syncthreads();

    // 32 threads: out[i,d] = (S[i,:]·W2[d,:])/(N-1) + b2[d]
    if (t < 32) {
        int jl = t >> 3;
        int d  = t & 7;
        float v = 0.f;
        #pragma unroll
        for (int hh = 0; hh < HH; hh++)
            v += sVal[hh * 4 + jl] * W2[d * HH + hh];
        out[(blockIdx.x * 4 + jl) * DD + d] =
            v * (1.f / (float)(NN - 1)) + b2[d];
    }
}

extern "C" void kernel_launch(void* const* d_in, const int* in_sizes, int n_in,
                              void* d_out, int out_size) {
    const float* msg = (const float*)d_in[0];  // [2048, 8]
    const float* W1  = (const float*)d_in[1];  // [64, 16]
    const float* b1  = (const float*)d_in[2];  // [64]
    const float* W2  = (const float*)d_in[3];  // [8, 64]
    const float* b2  = (const float*)d_in[4];  // [8]
    float* out = (float*)d_out;                // [2048, 8]

    (void)in_sizes; (void)n_in; (void)out_size;

    gnn_build_kernel<<<HH, 512>>>(msg, W1, b1);
    gnn_query_kernel<<<NN / 4, 256>>>(msg, W1, b1, W2, b2, out);
}